// round 15
// baseline (speedup 1.0000x reference)
#include <cuda_runtime.h>

// AELoss: pred/target (64,4,256,256) fp32, match (64,128,2,2) int32.
// out[0] = 0.25 * sum_b pull_b, out[1] = 0.25 * sum_b push_b
//
// pull_b = sum_{n,c} (tl-br)^2 / 2 / N        (since tl-me = (tl-br)/2)
// push_b = sum_{i!=j} relu(1 - |s_i - s_j|) / (N*(N-1)),  s_i = sum_c (tl+br)/2
//
// FINAL (frozen) — session best 7.936us total, kernel 6.464us.
// Adjudication over 15 rounds:
//   WIN     (-2.0us): fire-and-forget RED.ADD tail (no read-back reduction)
//   MARGINAL: two-warp split of the tail atomics (this version)
//   NEUTRAL: kernel fusion, ILP splits, cluster gather-halving, 256-thread
//            j-split, L2 evict_last policy, atomic trees
//   NEGATIVE: in-kernel fenced zeroing (+1.1us), 2-level completion tree
// Remaining cost = launch ramp (~5K cyc in-kernel) + graph dispatch (~1.5us
// outside): not .cu-addressable. Body is slack under the ramp (four
// structurally different bodies timed identically at 6.69us).

#define B_IMGS 64
#define N_KP   128
#define C_CH   4
#define HW     65536   // 256*256
#define W_DIM  256

__global__ __launch_bounds__(N_KP, 1)
void ae_kernel(const float* __restrict__ pred,
               const float* __restrict__ target,
               const int*   __restrict__ match,
               float*       __restrict__ out) {
    const int b = blockIdx.x;
    const int n = threadIdx.x;

    __shared__ float s_me[N_KP];
    __shared__ float s_red[8];   // 4 warps x 2 values

    // match[b, n, {tl,br}, {y,x}] -- one int4 per (b,n), issued first
    const int4 m = __ldg(reinterpret_cast<const int4*>(match) + b * N_KP + n);
    const int tl_off = m.x * W_DIM + m.y;
    const int br_off = m.z * W_DIM + m.w;

    const float* __restrict__ p = pred   + (size_t)b * C_CH * HW;
    const float* __restrict__ t = target + (size_t)b * C_CH * HW;

    float pull = 0.0f;
    float s    = 0.0f;
    #pragma unroll
    for (int c = 0; c < C_CH; ++c) {
        const float tl = __ldg(p + c * HW + tl_off);
        const float br = __ldg(t + c * HW + br_off);
        const float d = tl - br;
        pull += 0.5f * d * d;
        s    += 0.5f * (tl + br);
    }
    s_me[n] = s;
    __syncthreads();

    // push over all j (smem broadcast, vectorized); subtract the j==n term (==1)
    float push = -1.0f;
    const float4* __restrict__ s4 = reinterpret_cast<const float4*>(s_me);
    #pragma unroll
    for (int j = 0; j < N_KP / 4; ++j) {
        const float4 v = s4[j];
        push += fmaxf(0.0f, 1.0f - fabsf(s - v.x));
        push += fmaxf(0.0f, 1.0f - fabsf(s - v.y));
        push += fmaxf(0.0f, 1.0f - fabsf(s - v.z));
        push += fmaxf(0.0f, 1.0f - fabsf(s - v.w));
    }

    // block reduction of (pull, push)
    #pragma unroll
    for (int off = 16; off > 0; off >>= 1) {
        pull += __shfl_down_sync(0xFFFFFFFFu, pull, off);
        push += __shfl_down_sync(0xFFFFFFFFu, push, off);
    }
    const int warp = n >> 5;
    const int lane = n & 31;
    if (lane == 0) {
        s_red[warp]     = pull;
        s_red[4 + warp] = push;
    }
    __syncthreads();

    // fire-and-forget global reduction, one RED.ADD from each of two warps
    if (n == 0) {
        const float pu = s_red[0] + s_red[1] + s_red[2] + s_red[3];
        atomicAdd(&out[0], pu * (0.25f / (float)N_KP));
    } else if (n == 32) {
        const float ph = s_red[4] + s_red[5] + s_red[6] + s_red[7];
        atomicAdd(&out[1], ph * (0.25f / (float)(N_KP * (N_KP - 1))));
    }
}

extern "C" void kernel_launch(void* const* d_in, const int* in_sizes, int n_in,
                              void* d_out, int out_size) {
    const float* pred   = (const float*)d_in[0];
    const float* target = (const float*)d_in[1];
    const int*   match  = (const int*)d_in[2];
    float* out = (float*)d_out;

    cudaMemsetAsync(out, 0, 2 * sizeof(float));
    ae_kernel<<<B_IMGS, N_KP>>>(pred, target, match, out);
}

// round 16
// speedup vs baseline: 1.0332x; 1.0332x over previous
#include <cuda_runtime.h>

// AELoss: pred/target (64,4,256,256) fp32, match (64,128,2,2) int32.
// out[0] = 0.25 * sum_b pull_b, out[1] = 0.25 * sum_b push_b
//
// pull_b = sum_{n,c} (tl-br)^2 / 2 / N        (since tl-me = (tl-br)/2)
// push_b = sum_{i!=j} relu(1 - |s_i - s_j|) / (N*(N-1)),  s_i = sum_c (tl+br)/2
//
// FINAL (frozen) — session best 7.936us total, kernel 6.432us.
// Adjudication over 16 rounds:
//   WIN     (-2.0us): fire-and-forget RED.ADD tail (no read-back reduction)
//   MARGINAL: two-warp split of the tail atomics (this version)
//   NEUTRAL: kernel fusion, ILP splits, cluster gather-halving, 256-thread
//            j-split, L2 evict_last policy, atomic trees
//   NEGATIVE: in-kernel fenced zeroing (+1.1us), 2-level completion tree
// Remaining cost = launch ramp (~5K cyc in-kernel) + graph dispatch (~1.5us
// outside): not .cu-addressable. Body is slack under the ramp (four
// structurally different bodies timed identically).

#define B_IMGS 64
#define N_KP   128
#define C_CH   4
#define HW     65536   // 256*256
#define W_DIM  256

__global__ __launch_bounds__(N_KP, 1)
void ae_kernel(const float* __restrict__ pred,
               const float* __restrict__ target,
               const int*   __restrict__ match,
               float*       __restrict__ out) {
    const int b = blockIdx.x;
    const int n = threadIdx.x;

    __shared__ float s_me[N_KP];
    __shared__ float s_red[8];   // 4 warps x 2 values

    // match[b, n, {tl,br}, {y,x}] -- one int4 per (b,n), issued first
    const int4 m = __ldg(reinterpret_cast<const int4*>(match) + b * N_KP + n);
    const int tl_off = m.x * W_DIM + m.y;
    const int br_off = m.z * W_DIM + m.w;

    const float* __restrict__ p = pred   + (size_t)b * C_CH * HW;
    const float* __restrict__ t = target + (size_t)b * C_CH * HW;

    float pull = 0.0f;
    float s    = 0.0f;
    #pragma unroll
    for (int c = 0; c < C_CH; ++c) {
        const float tl = __ldg(p + c * HW + tl_off);
        const float br = __ldg(t + c * HW + br_off);
        const float d = tl - br;
        pull += 0.5f * d * d;
        s    += 0.5f * (tl + br);
    }
    s_me[n] = s;
    __syncthreads();

    // push over all j (smem broadcast, vectorized); subtract the j==n term (==1)
    float push = -1.0f;
    const float4* __restrict__ s4 = reinterpret_cast<const float4*>(s_me);
    #pragma unroll
    for (int j = 0; j < N_KP / 4; ++j) {
        const float4 v = s4[j];
        push += fmaxf(0.0f, 1.0f - fabsf(s - v.x));
        push += fmaxf(0.0f, 1.0f - fabsf(s - v.y));
        push += fmaxf(0.0f, 1.0f - fabsf(s - v.z));
        push += fmaxf(0.0f, 1.0f - fabsf(s - v.w));
    }

    // block reduction of (pull, push)
    #pragma unroll
    for (int off = 16; off > 0; off >>= 1) {
        pull += __shfl_down_sync(0xFFFFFFFFu, pull, off);
        push += __shfl_down_sync(0xFFFFFFFFu, push, off);
    }
    const int warp = n >> 5;
    const int lane = n & 31;
    if (lane == 0) {
        s_red[warp]     = pull;
        s_red[4 + warp] = push;
    }
    __syncthreads();

    // fire-and-forget global reduction, one RED.ADD from each of two warps
    if (n == 0) {
        const float pu = s_red[0] + s_red[1] + s_red[2] + s_red[3];
        atomicAdd(&out[0], pu * (0.25f / (float)N_KP));
    } else if (n == 32) {
        const float ph = s_red[4] + s_red[5] + s_red[6] + s_red[7];
        atomicAdd(&out[1], ph * (0.25f / (float)(N_KP * (N_KP - 1))));
    }
}

extern "C" void kernel_launch(void* const* d_in, const int* in_sizes, int n_in,
                              void* d_out, int out_size) {
    const float* pred   = (const float*)d_in[0];
    const float* target = (const float*)d_in[1];
    const int*   match  = (const int*)d_in[2];
    float* out = (float*)d_out;

    cudaMemsetAsync(out, 0, 2 * sizeof(float));
    ae_kernel<<<B_IMGS, N_KP>>>(pred, target, match, out);
}